// round 17
// baseline (speedup 1.0000x reference)
#include <cuda_runtime.h>
#include <math.h>

#define HH 512
#define WW 512
#define NB 64
#define PD 15
#define RB 32                  // rows per tile
#define CW 256                 // cols per tile
#define BANDS (HH / RB)        // 16
#define CSPLIT (WW / CW)       // 2
#define NPART (BANDS * CSPLIT) // 32 tiles per image
#define GG 4                   // rows per smem group
#define NGROUPS (RB / GG)      // 8
#define NTH 128
#define HB 288                 // halo buffer width (cols C0-16 .. C0+271)
#define SBW 296                // swizzled: scol(287)=295 -> 296
#define NBLOCKS (NPART * NB)   // 2048

__device__ __forceinline__ int scol(int c) { return c + (c >> 5); }

__device__ __forceinline__ float fast_sigmoid(float x) {
    float th;
    asm("tanh.approx.f32 %0, %1;" : "=f"(th) : "f"(0.5f * x));
    return fmaf(0.5f, th, 0.5f);
}

__device__ float g_part[NB * NPART * 2];
__device__ unsigned int g_count = 0;

// float2 mask load at (row r, global col gc), zero outside [0,WW)
__device__ __forceinline__ float2 mload2(const float2* mb2, int r, int gc) {
    if ((unsigned)gc < WW) return mb2[r * (WW / 2) + (gc >> 1)];
    return make_float2(0.f, 0.f);
}

__global__ __launch_bounds__(NTH, 14)
void fused_kernel(const float* __restrict__ pred, const float* __restrict__ mask,
                  float* __restrict__ out) {
    __shared__ float buf[2][GG][SBW];       // 9,472 B
    __shared__ float s_i[4], s_u[4];
    __shared__ bool amLast;

    const int t    = threadIdx.x;
    const int bx   = blockIdx.x;            // 0..31 tile-in-image
    const int b    = blockIdx.y;
    const int band = bx >> 1;
    const int cx   = bx & 1;
    const int r0   = band * RB;
    const int C0   = cx * CW;
    const float*  mb  = mask + (size_t)b * HH * WW;
    const float*  pb  = pred + (size_t)b * HH * WW;
    const float2* mb2 = reinterpret_cast<const float2*>(mb);

    // phase-A ownership: main float2 at buffer idx (2t, 2t+1); threads 0..15
    // additionally own idx (256+2t, 257+2t). Buffer idx i <-> global col C0-16+i.
    const int gcM = C0 - 16 + 2 * t;
    const bool hasE = (t < 16);
    const int gcE = C0 + 240 + 2 * t;

    // zero both buffers once
    #pragma unroll
    for (int i = t; i < 2 * GG * SBW; i += NTH) ((float*)buf)[i] = 0.f;

    // vertical running-sum init: rows [r0-15, r0+14] (max 494 < 512)
    float2 sm = {0.f, 0.f}, se = {0.f, 0.f};
    {
        float2 A0 = {0,0}, A1 = {0,0}, E0 = {0,0}, E1 = {0,0};
        #pragma unroll
        for (int j = 0; j < 30; j += 2) {
            int g0 = r0 - PD + j, g1 = g0 + 1;
            if (g0 >= 0) { float2 v = mload2(mb2, g0, gcM); A0.x += v.x; A0.y += v.y;
                           if (hasE) { float2 w = mload2(mb2, g0, gcE); E0.x += w.x; E0.y += w.y; } }
            if (g1 >= 0) { float2 v = mload2(mb2, g1, gcM); A1.x += v.x; A1.y += v.y;
                           if (hasE) { float2 w = mload2(mb2, g1, gcE); E1.x += w.x; E1.y += w.y; } }
        }
        sm.x = A0.x + A1.x; sm.y = A0.y + A1.y;
        se.x = E0.x + E1.x; se.y = E0.y + E1.y;
    }

    __syncthreads();   // zeroing complete before staged interior writes

    // ---- prologue: phase A for group 0 into buf[0] ----
    #pragma unroll
    for (int rr = 0; rr < GG; ++rr) {
        int gr = r0 + rr;
        float2 lead = (gr + PD < HH) ? mload2(mb2, gr + PD, gcM) : make_float2(0,0);
        sm.x += lead.x; sm.y += lead.y;
        buf[0][rr][scol(2*t + 0)] = sm.x;
        buf[0][rr][scol(2*t + 1)] = sm.y;
        if (hasE) {
            float2 le = (gr + PD < HH) ? mload2(mb2, gr + PD, gcE) : make_float2(0,0);
            se.x += le.x; se.y += le.y;
            buf[0][rr][scol(256 + 2*t + 0)] = se.x;
            buf[0][rr][scol(256 + 2*t + 1)] = se.y;
        }
        float2 tr = (gr - PD >= 0) ? mload2(mb2, gr - PD, gcM) : make_float2(0,0);
        sm.x -= tr.x; sm.y -= tr.y;
        if (hasE) {
            float2 te = (gr - PD >= 0) ? mload2(mb2, gr - PD, gcE) : make_float2(0,0);
            se.x -= te.x; se.y -= te.y;
        }
    }
    __syncthreads();

    const float inv = 1.0f / 961.0f;
    float fi = 0.f, fu = 0.f;

    // phase-B mapping: warp per row (4 rows), 8 cols per lane
    const int rg   = t >> 5;
    const int lane = t & 31;
    const int lc0  = lane * 8;              // local output col base

    for (int g = 0; g < NGROUPS; ++g) {
        // ---- phase A for group g+1 (overlaps phase B) ----
        if (g + 1 < NGROUPS) {
            const int rbase = r0 + (g + 1) * GG;
            float* bw = &buf[(g + 1) & 1][0][0];
            #pragma unroll
            for (int rr = 0; rr < GG; ++rr) {
                int gr = rbase + rr;
                float2 lead = (gr + PD < HH) ? mload2(mb2, gr + PD, gcM) : make_float2(0,0);
                sm.x += lead.x; sm.y += lead.y;
                bw[rr * SBW + scol(2*t + 0)] = sm.x;
                bw[rr * SBW + scol(2*t + 1)] = sm.y;
                if (hasE) {
                    float2 le = (gr + PD < HH) ? mload2(mb2, gr + PD, gcE) : make_float2(0,0);
                    se.x += le.x; se.y += le.y;
                    bw[rr * SBW + scol(256 + 2*t + 0)] = se.x;
                    bw[rr * SBW + scol(256 + 2*t + 1)] = se.y;
                }
                float2 tr = (gr - PD >= 0) ? mload2(mb2, gr - PD, gcM) : make_float2(0,0);
                sm.x -= tr.x; sm.y -= tr.y;
                if (hasE) {
                    float2 te = (gr - PD >= 0) ? mload2(mb2, gr - PD, gcE) : make_float2(0,0);
                    se.x -= te.x; se.y -= te.y;
                }
            }
        }

        // ---- phase B for group g from buf[g&1] ----
        {
            const int grB = r0 + g * GG + rg;
            const float* br   = &buf[g & 1][rg][0];
            const float* mrow = mb + grB * WW + C0 + lc0;
            const float* prow = pb + grB * WW + C0 + lc0;

            // own chunk: buffer idx [lc0+1, lc0+8] (banks all distinct)
            float o0 = br[scol(lc0 + 1)], o1 = br[scol(lc0 + 2)];
            float o2 = br[scol(lc0 + 3)], o3 = br[scol(lc0 + 4)];
            float o4 = br[scol(lc0 + 5)], o5 = br[scol(lc0 + 6)];
            float o6 = br[scol(lc0 + 7)], o7 = br[scol(lc0 + 8)];
            float S = ((o0 + o1) + (o2 + o3)) + ((o4 + o5) + (o6 + o7));
            float U = S - o7;

            // window idx [lc0+1, lc0+31] = S + S(+1) + S(+2) + U(+3)
            float s1f = __shfl_down_sync(0xffffffffu, S, 1);
            float s2f = __shfl_down_sync(0xffffffffu, S, 2);
            float u3f = __shfl_down_sync(0xffffffffu, U, 3);
            float hs = S + s1f + s2f + u3f;

            // lanes 29..31: shuffle sources invalid -> direct LDS (halo in buffer)
            if (lane >= 29) {
                float a0 = 0.f, a1 = 0.f, a2 = 0.f, a3 = 0.f;
                #pragma unroll
                for (int j = 9; j < 29; j += 4) {
                    a0 += br[scol(lc0 + j + 0)];
                    a1 += br[scol(lc0 + j + 1)];
                    a2 += br[scol(lc0 + j + 2)];
                    a3 += br[scol(lc0 + j + 3)];
                }
                a0 += br[scol(lc0 + 29)];
                a1 += br[scol(lc0 + 30)];
                a2 += br[scol(lc0 + 31)];
                hs = S + (a0 + a1) + (a2 + a3);
            }

            float own[8] = {o0, o1, o2, o3, o4, o5, o6, o7};

            #pragma unroll
            for (int h = 0; h < 2; ++h) {
                float4 m4 = *reinterpret_cast<const float4*>(mrow + h * 4);
                float4 p4 = *reinterpret_cast<const float4*>(prow + h * 4);
                float mk[4] = {m4.x, m4.y, m4.z, m4.w};
                float pr[4] = {p4.x, p4.y, p4.z, p4.w};
                #pragma unroll
                for (int q = 0; q < 4; ++q) {
                    int lc = lc0 + h * 4 + q;
                    float avg  = hs * inv;
                    float weit = fmaf(5.f, fabsf(avg - mk[q]), 1.f);
                    float p    = fast_sigmoid(pr[q]);
                    fi = fmaf(p * mk[q], weit, fi);
                    fu = fmaf(p + mk[q], weit, fu);
                    hs += br[scol(lc + 32)] - own[h * 4 + q];
                }
            }
        }
        __syncthreads();
    }

    // ---- block reduce 128 -> 1 ----
    #pragma unroll
    for (int o = 16; o; o >>= 1) {
        fi += __shfl_down_sync(0xffffffffu, fi, o);
        fu += __shfl_down_sync(0xffffffffu, fu, o);
    }
    int wid = t >> 5;
    if (lane == 0) { s_i[wid] = fi; s_u[wid] = fu; }
    __syncthreads();
    if (wid == 0) {
        float ti = (lane < 4) ? s_i[lane] : 0.f;
        float tu = (lane < 4) ? s_u[lane] : 0.f;
        #pragma unroll
        for (int o = 2; o; o >>= 1) {
            ti += __shfl_down_sync(0xffffffffu, ti, o);
            tu += __shfl_down_sync(0xffffffffu, tu, o);
        }
        if (lane == 0) {
            g_part[(b * NPART + bx) * 2 + 0] = ti;
            g_part[(b * NPART + bx) * 2 + 1] = tu;
            __threadfence();
            unsigned int done = atomicAdd(&g_count, 1u);
            amLast = (done == NBLOCKS - 1);
        }
    }
    __syncthreads();

    // ---- last CTA: finalize ----
    if (amLast) {
        double w = 0.0;
        if (t < NB) {
            double it = 0.0, un = 0.0;
            #pragma unroll
            for (int p = 0; p < NPART; ++p) {
                it += (double)g_part[(t * NPART + p) * 2 + 0];
                un += (double)g_part[(t * NPART + p) * 2 + 1];
            }
            w = 1.0 - (2.0 * it + 0.5) / (un + 0.5);
        }
        #pragma unroll
        for (int o = 16; o; o >>= 1) w += __shfl_down_sync(0xffffffffu, w, o);
        __shared__ double sh[2];
        if (t < 64 && (t & 31) == 0) sh[t >> 5] = w;
        __syncthreads();
        if (t == 0) {
            out[0] = (float)((sh[0] + sh[1]) / (double)NB);
            g_count = 0;   // reset for next graph replay
        }
    }
}

extern "C" void kernel_launch(void* const* d_in, const int* in_sizes, int n_in,
                              void* d_out, int out_size) {
    const float* pred = (const float*)d_in[0];
    const float* mask = (const float*)d_in[1];
    float* out = (float*)d_out;

    fused_kernel<<<dim3(NPART, NB), NTH>>>(pred, mask, out);
}